// round 1
// baseline (speedup 1.0000x reference)
#include <cuda_runtime.h>
#include <cuda_bf16.h>

// Problem constants
#define NOBS    64     // input feature dim
#define HID     100    // hidden width
#define LAYERS  100    // number of hidden layers
#define SAMPLES 64     // samples per block
#define SP      68     // h row stride in floats (mult of 4 for 16B align; 68%32=4 limits store conflicts)
#define NTHREADS 200   // blockDim = (8 sample-groups, 25 output-groups)

// ---- packed f32x2 helpers (Blackwell sm_103a) ----
__device__ __forceinline__ unsigned long long dup2(float x) {
    unsigned long long r;
    asm("mov.b64 %0, {%1, %1};" : "=l"(r) : "f"(x));
    return r;
}
__device__ __forceinline__ unsigned long long ffma2(unsigned long long a,
                                                    unsigned long long b,
                                                    unsigned long long c) {
    unsigned long long d;
    asm("fma.rn.f32x2 %0, %1, %2, %3;" : "=l"(d) : "l"(a), "l"(b), "l"(c));
    return d;
}

extern __shared__ float smem[];  // hbuf0[HID][SP], hbuf1[HID][SP]

// One dense layer: hout[j][s] = leaky(sum_i hin[i][s] * Wl[i][j] + bl[j])
// Thread (sg, og) computes samples [8*sg, 8*sg+8) x outputs [4*og, 4*og+4).
// Samples are packed in f32x2 pairs (so h loads are direct LDS.128 -> operand pairs).
template <int K>
__device__ __forceinline__ void dense_layer(const float* __restrict__ Wl,
                                            const float* __restrict__ bl,
                                            const float* hin, float* hout,
                                            int sg, int og) {
    const int s0 = sg * 8;
    const int j0 = og * 4;

    unsigned long long acc[4][4];  // [sample-pair p][output jj]
    {
        unsigned long long b0 = dup2(bl[j0 + 0]);
        unsigned long long b1 = dup2(bl[j0 + 1]);
        unsigned long long b2 = dup2(bl[j0 + 2]);
        unsigned long long b3 = dup2(bl[j0 + 3]);
#pragma unroll
        for (int p = 0; p < 4; p++) {
            acc[p][0] = b0; acc[p][1] = b1; acc[p][2] = b2; acc[p][3] = b3;
        }
    }

#pragma unroll 4
    for (int i = 0; i < K; i++) {
        // 4 weights for this i, outputs j0..j0+3 (16B aligned: rows are 100 floats, j0 mult of 4)
        float4 w = *reinterpret_cast<const float4*>(Wl + i * HID + j0);
        unsigned long long wd0 = dup2(w.x);
        unsigned long long wd1 = dup2(w.y);
        unsigned long long wd2 = dup2(w.z);
        unsigned long long wd3 = dup2(w.w);

        // 8 samples = 4 f32x2 pairs, two LDS.128 (base 16B-aligned: SP*4=272 mult of 16, s0*4=32B mult of 16)
        const ulonglong2* hp = reinterpret_cast<const ulonglong2*>(hin + i * SP + s0);
        ulonglong2 h01 = hp[0];
        ulonglong2 h23 = hp[1];
        unsigned long long hv[4] = {h01.x, h01.y, h23.x, h23.y};

#pragma unroll
        for (int p = 0; p < 4; p++) {
            acc[p][0] = ffma2(hv[p], wd0, acc[p][0]);
            acc[p][1] = ffma2(hv[p], wd1, acc[p][1]);
            acc[p][2] = ffma2(hv[p], wd2, acc[p][2]);
            acc[p][3] = ffma2(hv[p], wd3, acc[p][3]);
        }
    }

    // LeakyReLU + store (sample-pairs are contiguous -> vectorized 8B shared stores)
#pragma unroll
    for (int jj = 0; jj < 4; jj++) {
#pragma unroll
        for (int p = 0; p < 4; p++) {
            float2 v = *reinterpret_cast<float2*>(&acc[p][jj]);
            v.x = v.x >= 0.0f ? v.x : 0.01f * v.x;
            v.y = v.y >= 0.0f ? v.y : 0.01f * v.y;
            *reinterpret_cast<float2*>(hout + (j0 + jj) * SP + s0 + 2 * p) = v;
        }
    }
}

__global__ void __launch_bounds__(NTHREADS, 3)
mlp_kernel(const float* __restrict__ x,
           const float* __restrict__ W_in, const float* __restrict__ b_in,
           const float* __restrict__ Ws,   const float* __restrict__ bs,
           const float* __restrict__ W_out, const float* __restrict__ b_out,
           float* __restrict__ out, int nsamples) {
    float* hbuf0 = smem;
    float* hbuf1 = smem + HID * SP;

    const int sg = threadIdx.x;     // 0..7   sample group
    const int og = threadIdx.y;     // 0..24  output group
    const int t  = sg + 8 * og;     // 0..199
    const int sbase = blockIdx.x * SAMPLES;

    // Load x tile (transposed) into hbuf0 rows 0..63
    for (int idx = t; idx < NOBS * SAMPLES; idx += NTHREADS) {
        int i = idx % NOBS;
        int s = idx / NOBS;
        int gs = sbase + s;
        float v = (gs < nsamples) ? x[gs * NOBS + i] : 0.0f;
        hbuf0[i * SP + s] = v;
    }
    __syncthreads();

    // Input layer: K=64
    dense_layer<NOBS>(W_in, b_in, hbuf0, hbuf1, sg, og);

    // 100 hidden layers, ping-pong
    for (int l = 0; l < LAYERS; l++) {
        __syncthreads();
        const float* hin = (l & 1) ? hbuf0 : hbuf1;
        float*       hout = (l & 1) ? hbuf1 : hbuf0;
        dense_layer<HID>(Ws + (size_t)l * HID * HID, bs + l * HID, hin, hout, sg, og);
    }
    __syncthreads();
    // After l=99 (odd): final activations in hbuf1.

    // Output head: one thread per sample (conflict-free LDS: consecutive t -> consecutive banks)
    if (t < SAMPLES) {
        int gs = sbase + t;
        if (gs < nsamples) {
            float a = b_out[0];
#pragma unroll 4
            for (int i = 0; i < HID; i++)
                a += hbuf1[i * SP + t] * W_out[i];
            a = tanhf(a);
            out[gs] = a * 4.5f + 5.5f;   // (tanh+1)/2*(10-1)+1
        }
    }
}

extern "C" void kernel_launch(void* const* d_in, const int* in_sizes, int n_in,
                              void* d_out, int out_size) {
    const float* x     = (const float*)d_in[0];
    const float* W_in  = (const float*)d_in[1];
    const float* b_in  = (const float*)d_in[2];
    const float* Ws    = (const float*)d_in[3];
    const float* bs    = (const float*)d_in[4];
    const float* W_out = (const float*)d_in[5];
    const float* b_out = (const float*)d_in[6];
    float* out = (float*)d_out;

    int nsamples = in_sizes[0] / NOBS;
    int nblocks  = (nsamples + SAMPLES - 1) / SAMPLES;

    size_t shmem = 2 * HID * SP * sizeof(float);  // 54,400 B > 48K default
    static bool attr_done = false;
    // setting the attribute is idempotent and not a stream op; safe under graph capture
    cudaFuncSetAttribute(mlp_kernel, cudaFuncAttributeMaxDynamicSharedMemorySize, (int)shmem);
    (void)attr_done;

    mlp_kernel<<<nblocks, dim3(8, 25), shmem>>>(x, W_in, b_in, Ws, bs, W_out, b_out,
                                                out, nsamples);
}